// round 4
// baseline (speedup 1.0000x reference)
#include <cuda_runtime.h>
#include <math.h>

#define B_   2
#define T_   1024
#define C_   1024
#define NH   16
#define NKV  4
#define HD   64
#define S_   2048
#define ROWS 2048
#define KVW  (NKV*HD)

// ---------------- scratch ----------------
__device__ float g_q [ROWS * C_];
__device__ float g_ao[ROWS * C_];
__device__ float g_invf[32];
__device__ float g_cos[ROWS * 32];
__device__ float g_sin[ROWS * 32];

// ---------------- helpers ----------------
__device__ __forceinline__ unsigned f2tf(float x) {
    unsigned u;
    asm("cvt.rna.tf32.f32 %0, %1;" : "=r"(u) : "f"(x));
    return u;
}
__device__ __forceinline__ void mma_tf32(float* c,
                                         unsigned a0, unsigned a1, unsigned a2, unsigned a3,
                                         unsigned b0, unsigned b1) {
    asm volatile(
        "mma.sync.aligned.m16n8k8.row.col.f32.tf32.tf32.f32 "
        "{%0,%1,%2,%3}, {%4,%5,%6,%7}, {%8,%9}, {%0,%1,%2,%3};"
        : "+f"(c[0]), "+f"(c[1]), "+f"(c[2]), "+f"(c[3])
        : "r"(a0), "r"(a1), "r"(a2), "r"(a3), "r"(b0), "r"(b1));
}
__device__ __forceinline__ void cpa16(unsigned s, const float* g) {
    asm volatile("cp.async.ca.shared.global [%0], [%1], 16;" :: "r"(s), "l"(g));
}
__device__ __forceinline__ void cpa_commit() { asm volatile("cp.async.commit_group;"); }

// ---------------- GEMM core: 128M x 64N tile, 128 threads, K=1024, cp.async x2 ----------------
#define AS 36
#define BS 72
#define GSM ((2*128*AS + 2*32*BS) * 4)   // 55296 B

__device__ __forceinline__ void gemm_main(const float* __restrict__ A,
                                          const float* __restrict__ Bw,
                                          int ldB, int m0, int n0,
                                          float acc[2][8][4], float* smf) {
    float* A_s = smf;
    float* B_s = smf + 2 * 128 * AS;
    const int tid = threadIdx.x;
    unsigned aBase = (unsigned)__cvta_generic_to_shared(A_s);
    unsigned bBase = (unsigned)__cvta_generic_to_shared(B_s);

    const int arow = tid >> 3, ac4 = (tid & 7) << 2;
    const int brow = tid >> 4, bc4 = (tid & 15) << 2;

    #pragma unroll
    for (int i = 0; i < 8; i++)
        cpa16(aBase + (((arow + i * 16) * AS + ac4) << 2),
              &A[(size_t)(m0 + arow + i * 16) * 1024 + ac4]);
    #pragma unroll
    for (int i = 0; i < 4; i++)
        cpa16(bBase + (((brow + i * 8) * BS + bc4) << 2),
              &Bw[(size_t)(brow + i * 8) * ldB + n0 + bc4]);
    cpa_commit();

    const int lane = tid & 31, warp = tid >> 5;
    const int tq = lane >> 2, tr = lane & 3;
    int buf = 0;
    for (int c = 0; c < 32; c++) {
        if (c < 31) {
            int kc = (c + 1) * 32;
            int nb = buf ^ 1;
            #pragma unroll
            for (int i = 0; i < 8; i++)
                cpa16(aBase + ((((nb * 128) + arow + i * 16) * AS + ac4) << 2),
                      &A[(size_t)(m0 + arow + i * 16) * 1024 + kc + ac4]);
            #pragma unroll
            for (int i = 0; i < 4; i++)
                cpa16(bBase + ((((nb * 32) + brow + i * 8) * BS + bc4) << 2),
                      &Bw[(size_t)(kc + brow + i * 8) * ldB + n0 + bc4]);
            cpa_commit();
            asm volatile("cp.async.wait_group 1;");
        } else {
            asm volatile("cp.async.wait_group 0;");
        }
        __syncthreads();

        const float* Ab = A_s + buf * 128 * AS;
        const float* Bb = B_s + buf * 32 * BS;
        #pragma unroll
        for (int ks = 0; ks < 4; ks++) {
            unsigned a[2][4];
            #pragma unroll
            for (int mt = 0; mt < 2; mt++) {
                const float* p = &Ab[(warp * 32 + mt * 16 + tq) * AS + ks * 8 + tr];
                a[mt][0] = f2tf(p[0]);
                a[mt][1] = f2tf(p[8 * AS]);
                a[mt][2] = f2tf(p[4]);
                a[mt][3] = f2tf(p[8 * AS + 4]);
            }
            #pragma unroll
            for (int nt = 0; nt < 8; nt++) {
                unsigned b0 = f2tf(Bb[(ks * 8 + tr) * BS + nt * 8 + tq]);
                unsigned b1 = f2tf(Bb[(ks * 8 + tr + 4) * BS + nt * 8 + tq]);
                mma_tf32(acc[0][nt], a[0][0], a[0][1], a[0][2], a[0][3], b0, b1);
                mma_tf32(acc[1][nt], a[1][0], a[1][1], a[1][2], a[1][3], b0, b1);
            }
        }
        __syncthreads();
        buf ^= 1;
    }
}

// rope rotate in registers: pairs (nt, nt+4)
__device__ __forceinline__ void rope_acc(float acc[2][8][4], int m0) {
    const int lane = threadIdx.x & 31, warp = threadIdx.x >> 5;
    const int tq = lane >> 2, tr = lane & 3;
    #pragma unroll
    for (int mt = 0; mt < 2; mt++) {
        int r0 = m0 + warp * 32 + mt * 16 + tq;
        int r1 = r0 + 8;
        #pragma unroll
        for (int nt = 0; nt < 4; nt++) {
            int i0 = nt * 8 + 2 * tr;
            float2 c0 = *(const float2*)&g_cos[r0 * 32 + i0];
            float2 s0 = *(const float2*)&g_sin[r0 * 32 + i0];
            float2 c1 = *(const float2*)&g_cos[r1 * 32 + i0];
            float2 s1 = *(const float2*)&g_sin[r1 * 32 + i0];
            float x1, x2;
            x1 = acc[mt][nt][0]; x2 = acc[mt][nt + 4][0];
            acc[mt][nt][0] = x1 * c0.x - x2 * s0.x;  acc[mt][nt + 4][0] = x2 * c0.x + x1 * s0.x;
            x1 = acc[mt][nt][1]; x2 = acc[mt][nt + 4][1];
            acc[mt][nt][1] = x1 * c0.y - x2 * s0.y;  acc[mt][nt + 4][1] = x2 * c0.y + x1 * s0.y;
            x1 = acc[mt][nt][2]; x2 = acc[mt][nt + 4][2];
            acc[mt][nt][2] = x1 * c1.x - x2 * s1.x;  acc[mt][nt + 4][2] = x2 * c1.x + x1 * s1.x;
            x1 = acc[mt][nt][3]; x2 = acc[mt][nt + 4][3];
            acc[mt][nt][3] = x1 * c1.y - x2 * s1.y;  acc[mt][nt + 4][3] = x2 * c1.y + x1 * s1.y;
        }
    }
}

// ---------------- merged QKV projection (+rope, +scatter) ----------------
__global__ __launch_bounds__(128, 4) void qkv_gemm(const float* __restrict__ x,
                                                   const float* __restrict__ Wq,
                                                   const float* __restrict__ Wk,
                                                   const float* __restrict__ Wv,
                                                   float* __restrict__ kout,
                                                   float* __restrict__ vout) {
    extern __shared__ float smf[];
    const int bx = blockIdx.x, m0 = blockIdx.y * 128;
    const float* Bw; int ldB, n0, mode;
    if (bx < 16)      { Bw = Wq; ldB = 1024; n0 = bx * 64;        mode = 0; }
    else if (bx < 20) { Bw = Wk; ldB = 256;  n0 = (bx - 16) * 64; mode = 1; }
    else              { Bw = Wv; ldB = 256;  n0 = (bx - 20) * 64; mode = 2; }

    float acc[2][8][4];
    #pragma unroll
    for (int i = 0; i < 2; i++)
        #pragma unroll
        for (int j = 0; j < 8; j++)
            #pragma unroll
            for (int k = 0; k < 4; k++) acc[i][j][k] = 0.f;

    gemm_main(x, Bw, ldB, m0, n0, acc, smf);

    if (mode != 2) rope_acc(acc, m0);

    const int lane = threadIdx.x & 31, warp = threadIdx.x >> 5;
    const int tq = lane >> 2, tr = lane & 3;
    #pragma unroll
    for (int mt = 0; mt < 2; mt++) {
        int r = m0 + warp * 32 + mt * 16 + tq;
        if (mode == 0) {
            float* p0 = &g_q[(size_t)r * C_ + n0];
            float* p1 = &g_q[(size_t)(r + 8) * C_ + n0];
            #pragma unroll
            for (int nt = 0; nt < 8; nt++) {
                *(float2*)&p0[nt * 8 + 2 * tr] = make_float2(acc[mt][nt][0], acc[mt][nt][1]);
                *(float2*)&p1[nt * 8 + 2 * tr] = make_float2(acc[mt][nt][2], acc[mt][nt][3]);
            }
        } else {
            int b = r >> 10, t = r & 1023;
            int kv = (mode == 1) ? (bx - 16) : (bx - 20);
            float* dst = (mode == 1) ? kout : vout;
            float* p0 = &dst[(size_t)((b * NKV + kv) * S_ + 1024 + t) * HD];
            float* p1 = &dst[(size_t)((b * NKV + kv) * S_ + 1024 + t + 8) * HD];
            #pragma unroll
            for (int nt = 0; nt < 8; nt++) {
                *(float2*)&p0[nt * 8 + 2 * tr] = make_float2(acc[mt][nt][0], acc[mt][nt][1]);
                *(float2*)&p1[nt * 8 + 2 * tr] = make_float2(acc[mt][nt][2], acc[mt][nt][3]);
            }
        }
    }
}

// ---------------- O projection ----------------
__global__ __launch_bounds__(128, 4) void o_gemm(const float* __restrict__ A,
                                                 const float* __restrict__ Wo,
                                                 float* __restrict__ out) {
    extern __shared__ float smf[];
    const int m0 = blockIdx.y * 128, n0 = blockIdx.x * 64;
    float acc[2][8][4];
    #pragma unroll
    for (int i = 0; i < 2; i++)
        #pragma unroll
        for (int j = 0; j < 8; j++)
            #pragma unroll
            for (int k = 0; k < 4; k++) acc[i][j][k] = 0.f;

    gemm_main(A, Wo, 1024, m0, n0, acc, smf);

    const int lane = threadIdx.x & 31, warp = threadIdx.x >> 5;
    const int tq = lane >> 2, tr = lane & 3;
    #pragma unroll
    for (int mt = 0; mt < 2; mt++) {
        int r = m0 + warp * 32 + mt * 16 + tq;
        float* p0 = &out[(size_t)r * C_ + n0];
        float* p1 = &out[(size_t)(r + 8) * C_ + n0];
        #pragma unroll
        for (int nt = 0; nt < 8; nt++) {
            *(float2*)&p0[nt * 8 + 2 * tr] = make_float2(acc[mt][nt][0], acc[mt][nt][1]);
            *(float2*)&p1[nt * 8 + 2 * tr] = make_float2(acc[mt][nt][2], acc[mt][nt][3]);
        }
    }
}

// ---------------- tables ----------------
__global__ void invf_init() {
    if (threadIdx.x < 32)
        g_invf[threadIdx.x] = (float)pow(10000.0, -(double)threadIdx.x / 32.0);
}
__global__ void rope_tab(const int* __restrict__ pidx) {
    int idx = blockIdx.x * blockDim.x + threadIdx.x;
    if (idx >= ROWS * 32) return;
    int i = idx & 31, row = idx >> 5;
    int p = min(max(pidx[row] + (row & 1023) + 1024, 0), 4095);
    float ang = (float)p * g_invf[i];
    float c, s;
    sincosf(ang, &s, &c);
    g_cos[idx] = c;
    g_sin[idx] = s;
}

// ---------------- cache halves copy ----------------
__global__ void copy_cache(const float* __restrict__ kc, const float* __restrict__ vc,
                           float* __restrict__ kout, float* __restrict__ vout) {
    int idx = blockIdx.x * blockDim.x + threadIdx.x;
    if (idx >= B_ * NKV * 1024 * 16) return;
    int d4 = idx & 15;
    int s  = (idx >> 4) & 1023;
    int bk = idx >> 14;
    int dst = ((bk * S_) + s) * 16 + d4;
    ((float4*)kout)[dst] = ((const float4*)kc)[idx];
    ((float4*)vout)[dst] = ((const float4*)vc)[idx];
}

// ---------------- Flash attention v3: cp.async double-buffered K/V, cvt-at-use ----------------
#define KP 68
#define VP 72
#define BUFO (64*KP + 64*VP)         // 8960 floats per buffer
#define ASM (2 * BUFO * 4)           // 71680 B

__global__ __launch_bounds__(256, 2) void attn_k(const float* __restrict__ kall,
                                                 const float* __restrict__ vall) {
    extern __shared__ float smf[];
    const int tid = threadIdx.x, lane = tid & 31, warp = tid >> 5;
    const int tq = lane >> 2, tr = lane & 3;
    const int qt = blockIdx.x, h = blockIdx.y, b = blockIdx.z;
    const float* kb = kall + (size_t)(b * NKV + (h >> 2)) * S_ * HD;
    const float* vb = vall + (size_t)(b * NKV + (h >> 2)) * S_ * HD;
    const int qrow = qt * 128 + warp * 16;

    unsigned sBase = (unsigned)__cvta_generic_to_shared(smf);
    const int frow = tid >> 4, fd4 = (tid & 15) << 2;   // fill: 16 rows per 256-thr pass

    // prologue: prefetch chunks 0 and 1
    #pragma unroll
    for (int bu = 0; bu < 2; bu++) {
        int c0 = bu * 64;
        unsigned base = sBase + bu * (BUFO * 4);
        #pragma unroll
        for (int i = 0; i < 4; i++) {
            int row = frow + i * 16;
            cpa16(base + ((row * KP + fd4) << 2), &kb[(size_t)(c0 + row) * HD + fd4]);
            cpa16(base + ((64 * KP + row * VP + fd4) << 2), &vb[(size_t)(c0 + row) * HD + fd4]);
        }
        cpa_commit();
    }

    // Q fragments (scale folded)
    unsigned qa[8][4];
    const float* qp = g_q + (size_t)(b * T_ + qrow) * C_ + h * HD;
    #pragma unroll
    for (int ks = 0; ks < 8; ks++) {
        qa[ks][0] = f2tf(qp[(size_t)tq * C_ + ks * 8 + tr] * 0.125f);
        qa[ks][1] = f2tf(qp[(size_t)(tq + 8) * C_ + ks * 8 + tr] * 0.125f);
        qa[ks][2] = f2tf(qp[(size_t)tq * C_ + ks * 8 + tr + 4] * 0.125f);
        qa[ks][3] = f2tf(qp[(size_t)(tq + 8) * C_ + ks * 8 + tr + 4] * 0.125f);
    }

    float m0 = -1e30f, m1 = -1e30f, l0 = 0.f, l1 = 0.f;
    float o[8][4];
    #pragma unroll
    for (int nt = 0; nt < 8; nt++)
        #pragma unroll
        for (int k = 0; k < 4; k++) o[nt][k] = 0.f;

    const int srcA = (lane & 28) | ((lane >> 1) & 1);
    const int srcB = srcA + 2;
    const bool eo = lane & 1;

    for (int c = 0; c < 32; c++) {
        const float* K_s = smf + (c & 1) * BUFO;
        const float* V_s = K_s + 64 * KP;
        if (c < 31) asm volatile("cp.async.wait_group 1;");
        else        asm volatile("cp.async.wait_group 0;");
        __syncthreads();

        // S = Q @ K^T
        float s[8][4];
        #pragma unroll
        for (int nt = 0; nt < 8; nt++)
            #pragma unroll
            for (int k = 0; k < 4; k++) s[nt][k] = 0.f;
        #pragma unroll
        for (int ks = 0; ks < 8; ks++)
            #pragma unroll
            for (int nt = 0; nt < 8; nt++) {
                unsigned b0 = f2tf(K_s[(nt * 8 + tq) * KP + ks * 8 + tr]);
                unsigned b1 = f2tf(K_s[(nt * 8 + tq) * KP + ks * 8 + tr + 4]);
                mma_tf32(s[nt], qa[ks][0], qa[ks][1], qa[ks][2], qa[ks][3], b0, b1);
            }

        // online softmax
        float mx0 = -1e30f, mx1 = -1e30f;
        #pragma unroll
        for (int nt = 0; nt < 8; nt++) {
            mx0 = fmaxf(mx0, fmaxf(s[nt][0], s[nt][1]));
            mx1 = fmaxf(mx1, fmaxf(s[nt][2], s[nt][3]));
        }
        mx0 = fmaxf(mx0, __shfl_xor_sync(0xffffffffu, mx0, 1));
        mx0 = fmaxf(mx0, __shfl_xor_sync(0xffffffffu, mx0, 2));
        mx1 = fmaxf(mx1, __shfl_xor_sync(0xffffffffu, mx1, 1));
        mx1 = fmaxf(mx1, __shfl_xor_sync(0xffffffffu, mx1, 2));
        float nm0 = fmaxf(m0, mx0), nm1 = fmaxf(m1, mx1);
        float al0 = __expf(m0 - nm0), al1 = __expf(m1 - nm1);
        m0 = nm0; m1 = nm1;
        float rs0 = 0.f, rs1 = 0.f;
        #pragma unroll
        for (int nt = 0; nt < 8; nt++) {
            s[nt][0] = __expf(s[nt][0] - m0);
            s[nt][1] = __expf(s[nt][1] - m0);
            s[nt][2] = __expf(s[nt][2] - m1);
            s[nt][3] = __expf(s[nt][3] - m1);
            rs0 += s[nt][0] + s[nt][1];
            rs1 += s[nt][2] + s[nt][3];
        }
        rs0 += __shfl_xor_sync(0xffffffffu, rs0, 1);
        rs0 += __shfl_xor_sync(0xffffffffu, rs0, 2);
        rs1 += __shfl_xor_sync(0xffffffffu, rs1, 1);
        rs1 += __shfl_xor_sync(0xffffffffu, rs1, 2);
        l0 = l0 * al0 + rs0;
        l1 = l1 * al1 + rs1;
        #pragma unroll
        for (int nt = 0; nt < 8; nt++) {
            o[nt][0] *= al0; o[nt][1] *= al0;
            o[nt][2] *= al1; o[nt][3] *= al1;
        }

        // O += P @ V (P reshaped C-frag -> A-frag via shuffles)
        #pragma unroll
        for (int ks = 0; ks < 8; ks++) {
            unsigned u0 = f2tf(s[ks][0]), u1 = f2tf(s[ks][1]);
            unsigned u2 = f2tf(s[ks][2]), u3 = f2tf(s[ks][3]);
            unsigned xa0 = __shfl_sync(0xffffffffu, u0, srcA);
            unsigned xa1 = __shfl_sync(0xffffffffu, u1, srcA);
            unsigned ya0 = __shfl_sync(0xffffffffu, u2, srcA);
            unsigned ya1 = __shfl_sync(0xffffffffu, u3, srcA);
            unsigned xb0 = __shfl_sync(0xffffffffu, u0, srcB);
            unsigned xb1 = __shfl_sync(0xffffffffu, u1, srcB);
            unsigned yb0 = __shfl_sync(0xffffffffu, u2, srcB);
            unsigned yb1 = __shfl_sync(0xffffffffu, u3, srcB);
            unsigned a0 = eo ? xa1 : xa0;
            unsigned a1 = eo ? ya1 : ya0;
            unsigned a2 = eo ? xb1 : xb0;
            unsigned a3 = eo ? yb1 : yb0;
            #pragma unroll
            for (int dt = 0; dt < 8; dt++) {
                unsigned b0 = f2tf(V_s[(ks * 8 + tr) * VP + dt * 8 + tq]);
                unsigned b1 = f2tf(V_s[(ks * 8 + tr + 4) * VP + dt * 8 + tq]);
                mma_tf32(o[dt], a0, a1, a2, a3, b0, b1);
            }
        }

        __syncthreads();   // all reads of this buffer done before refill
        if (c + 2 < 32) {
            int c0 = (c + 2) * 64;
            unsigned base = sBase + (c & 1) * (BUFO * 4);
            #pragma unroll
            for (int i = 0; i < 4; i++) {
                int row = frow + i * 16;
                cpa16(base + ((row * KP + fd4) << 2), &kb[(size_t)(c0 + row) * HD + fd4]);
                cpa16(base + ((64 * KP + row * VP + fd4) << 2), &vb[(size_t)(c0 + row) * HD + fd4]);
            }
            cpa_commit();
        }
    }

    float inv0 = 1.f / l0, inv1 = 1.f / l1;
    float* ob = g_ao + (size_t)(b * T_ + qrow) * C_ + h * HD;
    #pragma unroll
    for (int nt = 0; nt < 8; nt++) {
        *(float2*)&ob[(size_t)tq * C_ + nt * 8 + 2 * tr] =
            make_float2(o[nt][0] * inv0, o[nt][1] * inv0);
        *(float2*)&ob[(size_t)(tq + 8) * C_ + nt * 8 + 2 * tr] =
            make_float2(o[nt][2] * inv1, o[nt][3] * inv1);
    }
}

// ---------------- launch ----------------
extern "C" void kernel_launch(void* const* d_in, const int* in_sizes, int n_in,
                              void* d_out, int out_size) {
    const float* x    = (const float*)d_in[0];
    const float* kc   = (const float*)d_in[1];
    const float* vc   = (const float*)d_in[2];
    const int*   pidx = (const int*)  d_in[3];
    const float* Wq   = (const float*)d_in[4];
    const float* Wk   = (const float*)d_in[5];
    const float* Wv   = (const float*)d_in[6];
    const float* Wo   = (const float*)d_in[7];

    float* out  = (float*)d_out;
    float* kout = out + 2 * 1024 * 1024;
    float* vout = kout + 2 * 4 * 2048 * 64;

    float *gq, *gao;
    cudaGetSymbolAddress((void**)&gq,  g_q);
    cudaGetSymbolAddress((void**)&gao, g_ao);

    cudaFuncSetAttribute(qkv_gemm, cudaFuncAttributeMaxDynamicSharedMemorySize, GSM);
    cudaFuncSetAttribute(o_gemm,   cudaFuncAttributeMaxDynamicSharedMemorySize, GSM);
    cudaFuncSetAttribute(attn_k,   cudaFuncAttributeMaxDynamicSharedMemorySize, ASM);

    invf_init<<<1, 32>>>();
    rope_tab<<<(ROWS * 32) / 256, 256>>>(pidx);

    dim3 gqkv(24, 16);
    qkv_gemm<<<gqkv, 128, GSM>>>(x, Wq, Wk, Wv, kout, vout);

    int nc = B_ * NKV * 1024 * 16;
    copy_cache<<<(nc + 255) / 256, 256>>>(kc, vc, kout, vout);

    dim3 ga(T_ / 128, NH, B_);
    attn_k<<<ga, 256, ASM>>>(kout, vout);

    dim3 go(16, 16);
    o_gemm<<<go, 128, GSM>>>(gao, Wo, out);
}